// round 4
// baseline (speedup 1.0000x reference)
#include <cuda_runtime.h>
#include <math.h>

#define ADIM 6
#define ZDIM 32
#define HDIM 512
#define EDIM 1024
#define BATCH 256
#define TSTEPS 64

// output layout: h_seq[B,T,H] | z_seq | pm | ps | qm | qs (each [B,T,Z])
#define OFF_Z  (BATCH*TSTEPS*HDIM)
#define ZBLK   (BATCH*TSTEPS*ZDIM)
#define OFF_PM (OFF_Z + ZBLK)
#define OFF_PS (OFF_PM + ZBLK)
#define OFF_QM (OFF_PS + ZBLK)
#define OFF_QS (OFF_QM + ZBLK)

// scratch (device globals; no dynamic allocation allowed)
__device__ __align__(128) float g_preAZ[BATCH*TSTEPS*HDIM]; // b_az + a@W_az_a, [b][t][h]
__device__ __align__(128) float g_preHA[BATCH*TSTEPS*HDIM]; // b_ha + a@W_ha_a
__device__ __align__(128) float g_preHE[BATCH*TSTEPS*HDIM]; // b_he + e@W_he_e
__device__ __align__(128) float g_G[BATCH*3072];            // [gi(1536)|gh(1536)]
__device__ __align__(128) float g_h[BATCH*HDIM];
__device__ __align__(128) float g_x[BATCH*HDIM];
__device__ __align__(128) float g_z[BATCH*ZDIM];
__device__ __align__(128) float g_hahe[BATCH*1024];         // [ha(512)|he(512)]
__device__ __align__(128) float g_WazzT[ZDIM*HDIM];         // W_az[:, :32] transposed [k][h]
__device__ __align__(128) float g_Wha[HDIM*HDIM];           // W_ha[:, :512] packed

__device__ __forceinline__ float sigmoidf_(float x) { return 1.f / (1.f + expf(-x)); }
__device__ __forceinline__ float softplusf_(float x) {
    return fmaxf(x, 0.f) + log1pf(expf(-fabsf(x)));
}

// ---------------------------------------------------------------------------
// Pipelined SIMT GEMM core. 128 threads. Tile BM x BN, BK=16, micro TM x TN.
// Requires BM,BN in {32,64}, TM,TN in {4,8}, BM*BN == 128*TM*TN, K % 16 == 0.
// A row-major [.,lda], B row-major [BN rows, ldb] (acc = A * B^T tile).
// ---------------------------------------------------------------------------
template<int BM, int BN, int TM, int TN>
__device__ __forceinline__ void gemm_tile(
    const float* __restrict__ A, int lda,
    const float* __restrict__ B, int ldb,
    int K, float* As, float* Bs, float (&acc)[TM][TN])
{
    constexpr int LDA = BM + 4, LDB = BN + 4;
    constexpr int AREP = BM / 32, BREP = BN / 32;
    const int tid = threadIdx.x;
    const int lr = tid >> 2, lk = (tid & 3) << 2;
    const int tx = tid % (BN / TN);
    const int ty = tid / (BN / TN);

    float4 aReg[AREP], bReg[BREP];
    #pragma unroll
    for (int i = 0; i < AREP; i++)
        aReg[i] = *(const float4*)(A + (lr + 32*i)*lda + lk);
    #pragma unroll
    for (int i = 0; i < BREP; i++)
        bReg[i] = *(const float4*)(B + (lr + 32*i)*ldb + lk);

    for (int k0 = 16; k0 <= K; k0 += 16) {
        __syncthreads();
        #pragma unroll
        for (int i = 0; i < AREP; i++) {
            As[(lk+0)*LDA + lr + 32*i] = aReg[i].x;
            As[(lk+1)*LDA + lr + 32*i] = aReg[i].y;
            As[(lk+2)*LDA + lr + 32*i] = aReg[i].z;
            As[(lk+3)*LDA + lr + 32*i] = aReg[i].w;
        }
        #pragma unroll
        for (int i = 0; i < BREP; i++) {
            Bs[(lk+0)*LDB + lr + 32*i] = bReg[i].x;
            Bs[(lk+1)*LDB + lr + 32*i] = bReg[i].y;
            Bs[(lk+2)*LDB + lr + 32*i] = bReg[i].z;
            Bs[(lk+3)*LDB + lr + 32*i] = bReg[i].w;
        }
        __syncthreads();
        if (k0 < K) {
            #pragma unroll
            for (int i = 0; i < AREP; i++)
                aReg[i] = *(const float4*)(A + (lr + 32*i)*lda + k0 + lk);
            #pragma unroll
            for (int i = 0; i < BREP; i++)
                bReg[i] = *(const float4*)(B + (lr + 32*i)*ldb + k0 + lk);
        }
        #pragma unroll
        for (int kk = 0; kk < 16; kk++) {
            alignas(16) float a[TM];
            alignas(16) float b[TN];
            #pragma unroll
            for (int i = 0; i < TM/4; i++)
                *(float4*)(a + 4*i) = *(const float4*)(As + kk*LDA + ty*TM + 4*i);
            #pragma unroll
            for (int j = 0; j < TN/4; j++)
                *(float4*)(b + 4*j) = *(const float4*)(Bs + kk*LDB + tx*TN + 4*j);
            #pragma unroll
            for (int i = 0; i < TM; i++)
                #pragma unroll
                for (int j = 0; j < TN; j++)
                    acc[i][j] += a[i]*b[j];
        }
    }
}

// ---------------------------------------------------------------------------
__global__ void k_init(const float* __restrict__ prev_z, const float* __restrict__ prev_h) {
    int idx = blockIdx.x * 256 + threadIdx.x;
    if (idx < BATCH*HDIM) g_h[idx] = prev_h[idx];
    if (idx < BATCH*ZDIM) g_z[idx] = prev_z[idx];
}

// pack W_ha[:, :512] (row stride 518) and W_az[:, :32] transposed
__global__ void k_pack(const float* __restrict__ W_az, const float* __restrict__ W_ha) {
    int n = blockIdx.x;             // 0..511
    int tid = threadIdx.x;          // 256
    g_Wha[n*HDIM + tid]       = W_ha[n*(HDIM+ADIM) + tid];
    g_Wha[n*HDIM + tid + 256] = W_ha[n*(HDIM+ADIM) + tid + 256];
    if (tid < ZDIM) g_WazzT[tid*HDIM + n] = W_az[n*(ZDIM+ADIM) + tid];
}

// preAZ, preHA (action projections + biases). grid=64 (t), 256 thr
__global__ __launch_bounds__(256) void k_pre_act(
    const float* __restrict__ actions,
    const float* __restrict__ W_az, const float* __restrict__ b_az,
    const float* __restrict__ W_ha, const float* __restrict__ b_ha)
{
    __shared__ float waz[HDIM*ADIM];
    __shared__ float wha[HDIM*ADIM];
    __shared__ float baz[HDIM];
    __shared__ float bha[HDIM];
    __shared__ float act[BATCH*ADIM];
    const int t = blockIdx.x;
    const int tid = threadIdx.x;
    for (int e = tid; e < HDIM*ADIM; e += 256) {
        int h = e / ADIM, j = e - h*ADIM;
        waz[e] = W_az[h*(ZDIM+ADIM) + ZDIM + j];
        wha[e] = W_ha[h*(HDIM+ADIM) + HDIM + j];
    }
    for (int e = tid; e < HDIM; e += 256) { baz[e] = b_az[e]; bha[e] = b_ha[e]; }
    for (int e = tid; e < BATCH*ADIM; e += 256) {
        int b = e / ADIM, j = e - b*ADIM;
        act[e] = actions[(b*TSTEPS + t)*ADIM + j];
    }
    __syncthreads();
    for (int e = tid; e < BATCH*HDIM; e += 256) {
        int b = e >> 9, h = e & 511;
        float pa = baz[h], ph = bha[h];
        #pragma unroll
        for (int j = 0; j < ADIM; j++) {
            float a = act[b*ADIM + j];
            pa += a * waz[h*ADIM + j];
            ph += a * wha[h*ADIM + j];
        }
        int o = (b*TSTEPS + t)*HDIM + h;
        g_preAZ[o] = pa;
        g_preHA[o] = ph;
    }
}

// preHE = b_he + e @ W_he[:,512:].T   M=16384 (r=b*64+t), N=512, K=1024
// grid (256, 8), 128 thr
__global__ __launch_bounds__(128) void k_pre_he(
    const float* __restrict__ emb, const float* __restrict__ W_he,
    const float* __restrict__ b_he)
{
    __shared__ float As[16*68];
    __shared__ float Bs[16*68];
    const int m0 = blockIdx.x * 64;
    const int n0 = blockIdx.y * 64;
    float acc[8][4] = {};
    gemm_tile<64,64,8,4>(emb + (size_t)m0*EDIM, EDIM,
                         W_he + (size_t)n0*1536 + 512, 1536,
                         EDIM, As, Bs, acc);
    const int tx = threadIdx.x & 15, ty = threadIdx.x >> 4;
    #pragma unroll
    for (int i = 0; i < 8; i++) {
        int r = m0 + ty*8 + i, c = n0 + tx*4;
        float4 v = make_float4(acc[i][0] + b_he[c], acc[i][1] + b_he[c+1],
                               acc[i][2] + b_he[c+2], acc[i][3] + b_he[c+3]);
        *(float4*)(g_preHE + r*HDIM + c) = v;
    }
}

// x = relu(zmask @ WzzT + preAZ[t]). prologue only (t=0). grid=BATCH, 512 thr
__global__ void k_x(const float* __restrict__ dones, int t) {
    const int b = blockIdx.x, h = threadIdx.x;
    __shared__ float sz[ZDIM];
    if (h < ZDIM) sz[h] = g_z[b*ZDIM + h] * (1.f - dones[b*TSTEPS + t]);
    __syncthreads();
    float acc = g_preAZ[(b*TSTEPS + t)*HDIM + h];
    #pragma unroll
    for (int k = 0; k < ZDIM; k++) acc += sz[k] * g_WazzT[k*HDIM + h];
    g_x[b*HDIM + h] = fmaxf(acc, 0.f);
}

// G = [gi | gh]: [256, 3072], K=512. grid (4, 48), 128 thr
__global__ __launch_bounds__(128) void k_gates(
    const float* __restrict__ W_ih, const float* __restrict__ W_hh,
    const float* __restrict__ b_ih, const float* __restrict__ b_hh)
{
    __shared__ float As[16*68];
    __shared__ float Bs[16*68];
    const int m0 = blockIdx.x * 64;
    const int n0 = blockIdx.y * 64;
    const bool isI = (n0 < 1536);
    const float* A = isI ? g_x : g_h;
    const float* B = isI ? (W_ih + (size_t)n0*HDIM) : (W_hh + (size_t)(n0-1536)*HDIM);
    const float* bias = isI ? (b_ih + n0) : (b_hh + (n0-1536));
    float acc[8][4] = {};
    gemm_tile<64,64,8,4>(A + (size_t)m0*HDIM, HDIM, B, HDIM, HDIM, As, Bs, acc);
    const int tx = threadIdx.x & 15, ty = threadIdx.x >> 4;
    float b0 = bias[tx*4], b1 = bias[tx*4+1], b2 = bias[tx*4+2], b3 = bias[tx*4+3];
    #pragma unroll
    for (int i = 0; i < 8; i++) {
        float4 v = make_float4(acc[i][0]+b0, acc[i][1]+b1, acc[i][2]+b2, acc[i][3]+b3);
        *(float4*)(g_G + (m0 + ty*8 + i)*3072 + n0 + tx*4) = v;
    }
}

// GRU gate fuse. grid 512, 256 thr
__global__ void k_gru(float* __restrict__ out, int t) {
    int idx = blockIdx.x * 256 + threadIdx.x;  // 131072
    int b = idx >> 9, j = idx & 511;
    const float* Gb = g_G + b*3072;
    float r = sigmoidf_(Gb[j] + Gb[1536 + j]);
    float u = sigmoidf_(Gb[512 + j] + Gb[2048 + j]);
    float n = tanhf(Gb[1024 + j] + r * Gb[2560 + j]);
    float hp = g_h[idx];
    float h = (1.f - u)*n + u*hp;
    g_h[idx] = h;
    out[b*TSTEPS*HDIM + t*HDIM + j] = h;
}

// hahe = relu(h @ [Wha_h | Whe_h]^T + [preHA|preHE]). [256,1024], K=512.
// grid (8,16), 128 thr, tile 32x64
__global__ __launch_bounds__(128) void k_hahe(const float* __restrict__ W_he, int t) {
    __shared__ float As[16*36];
    __shared__ float Bs[16*68];
    const int m0 = blockIdx.x * 32;
    const int n0 = blockIdx.y * 64;
    const bool isHA = (n0 < 512);
    const float* B = isHA ? (g_Wha + (size_t)n0*HDIM) : (W_he + (size_t)(n0-512)*1536);
    const int ldb = isHA ? HDIM : 1536;
    const float* pre = isHA ? g_preHA : g_preHE;
    const int pc0 = isHA ? n0 : (n0 - 512);
    float acc[4][4] = {};
    gemm_tile<32,64,4,4>(g_h + (size_t)m0*HDIM, HDIM, B, ldb, HDIM, As, Bs, acc);
    const int tx = threadIdx.x & 15, ty = threadIdx.x >> 4;
    #pragma unroll
    for (int i = 0; i < 4; i++) {
        int b = m0 + ty*4 + i, c = tx*4;
        float4 p = *(const float4*)(pre + (b*TSTEPS + t)*HDIM + pc0 + c);
        float4 v = make_float4(fmaxf(acc[i][0]+p.x, 0.f), fmaxf(acc[i][1]+p.y, 0.f),
                               fmaxf(acc[i][2]+p.z, 0.f), fmaxf(acc[i][3]+p.w, 0.f));
        *(float4*)(g_hahe + b*1024 + n0 + c) = v;
    }
}

// heads: prior=ha@W_prior.T, post=he@W_post.T; softplus; rsample;
// then x[t+1] = relu(zmask @ WzzT + preAZ[t+1]). grid 4, 256 thr
__global__ __launch_bounds__(256) void k_heads(
    const float* __restrict__ W_prior, const float* __restrict__ b_prior,
    const float* __restrict__ W_post, const float* __restrict__ b_post,
    const float* __restrict__ post_noise, const float* __restrict__ dones,
    float* __restrict__ out, int t)
{
    __shared__ __align__(16) float pool[8320];
    float* Aha   = pool;          // 16*65 = 1040
    float* Ahe   = pool + 1040;   // 16*65
    float* Ws    = pool + 2080;   // 16*130 = 2080
    float* Spost = pool + 4160;   // 64*65 = 4160
    // phase-2 aliases (GEMM buffers dead by then)
    float* Wzz = pool;            // 32*64 = 2048 (over Aha+Ahe)
    float* sZ  = pool + 2080;     // 64*32 = 2048 (over Ws)

    const int m0 = blockIdx.x * 64;
    const int tid = threadIdx.x;
    const int tx = tid & 15, ty = tid >> 4;
    const int lr = tid >> 2, lk = (tid & 3) << 2;
    const int wr = tid >> 1, wk = (tid & 1) << 3;
    float acc[4][8] = {};
    const float* ApH = g_hahe + (m0 + lr)*1024 + lk;
    const float* ApE = ApH + 512;
    const float* Wrow = (wr < 64) ? (W_prior + wr*HDIM + wk) : (W_post + (wr-64)*HDIM + wk);
    for (int k0 = 0; k0 < HDIM; k0 += 16) {
        float4 a = *(const float4*)(ApH + k0);
        float4 e = *(const float4*)(ApE + k0);
        float4 w0 = *(const float4*)(Wrow + k0);
        float4 w1 = *(const float4*)(Wrow + k0 + 4);
        __syncthreads();
        Aha[(lk+0)*65+lr]=a.x; Aha[(lk+1)*65+lr]=a.y; Aha[(lk+2)*65+lr]=a.z; Aha[(lk+3)*65+lr]=a.w;
        Ahe[(lk+0)*65+lr]=e.x; Ahe[(lk+1)*65+lr]=e.y; Ahe[(lk+2)*65+lr]=e.z; Ahe[(lk+3)*65+lr]=e.w;
        Ws[(wk+0)*130+wr]=w0.x; Ws[(wk+1)*130+wr]=w0.y; Ws[(wk+2)*130+wr]=w0.z; Ws[(wk+3)*130+wr]=w0.w;
        Ws[(wk+4)*130+wr]=w1.x; Ws[(wk+5)*130+wr]=w1.y; Ws[(wk+6)*130+wr]=w1.z; Ws[(wk+7)*130+wr]=w1.w;
        __syncthreads();
        const float* Asel = (tx < 8) ? Aha : Ahe;
        #pragma unroll
        for (int kk = 0; kk < 16; kk++) {
            float av[4], bv[8];
            #pragma unroll
            for (int i = 0; i < 4; i++) av[i] = Asel[kk*65 + ty*4 + i];
            #pragma unroll
            for (int j = 0; j < 8; j++) bv[j] = Ws[kk*130 + tx*8 + j];
            #pragma unroll
            for (int i = 0; i < 4; i++)
                #pragma unroll
                for (int j = 0; j < 8; j++) acc[i][j] += av[i]*bv[j];
        }
    }
    #pragma unroll
    for (int i = 0; i < 4; i++)
        #pragma unroll
        for (int j = 0; j < 8; j++) {
            int c = tx*8 + j, r = ty*4 + i, b = m0 + r;
            if (c < 64) {
                float v = acc[i][j] + b_prior[c];
                if (c < 32) out[OFF_PM + b*TSTEPS*ZDIM + t*ZDIM + c] = v;
                else        out[OFF_PS + b*TSTEPS*ZDIM + t*ZDIM + (c-32)] = softplusf_(v);
            } else {
                Spost[r*65 + (c - 64)] = acc[i][j] + b_post[c - 64];
            }
        }
    __syncthreads();
    for (int s = tid; s < 64*ZDIM; s += 256) {
        int r = s >> 5, j = s & 31, b = m0 + r;
        float qm = Spost[r*65 + j];
        float qs = softplusf_(Spost[r*65 + 32 + j]);
        float eps = post_noise[(b*TSTEPS + t)*ZDIM + j];
        float z = qm + qs*eps;
        int o = b*TSTEPS*ZDIM + t*ZDIM + j;
        out[OFF_QM + o] = qm;
        out[OFF_QS + o] = qs;
        out[OFF_Z  + o] = z;
        if (t + 1 < TSTEPS)
            sZ[r*32 + j] = z * (1.f - dones[b*TSTEPS + t + 1]);
    }
    // phase 2: x[t+1] = relu(zmask @ WzzT + preAZ[t+1]) for rows m0..m0+63
    if (t + 1 < TSTEPS) {
        __syncthreads();
        const int col = tid & 63, rgrp = tid >> 6;
        for (int c = 0; c < 8; c++) {
            __syncthreads();
            #pragma unroll
            for (int i = 0; i < 8; i++) {
                int e = tid + i*256;
                Wzz[e] = g_WazzT[(e >> 6)*HDIM + c*64 + (e & 63)];
            }
            __syncthreads();
            #pragma unroll
            for (int rr = 0; rr < 16; rr++) {
                int r = rgrp + rr*4;
                int b = m0 + r;
                float accx = g_preAZ[(b*TSTEPS + t + 1)*HDIM + c*64 + col];
                #pragma unroll
                for (int k = 0; k < ZDIM; k++)
                    accx += sZ[r*32 + k] * Wzz[k*64 + col];
                g_x[b*HDIM + c*64 + col] = fmaxf(accx, 0.f);
            }
        }
    }
}

extern "C" void kernel_launch(void* const* d_in, const int* in_sizes, int n_in,
                              void* d_out, int out_size) {
    const float* prev_z   = (const float*)d_in[0];
    const float* prev_h   = (const float*)d_in[1];
    const float* actions  = (const float*)d_in[2];
    const float* emb      = (const float*)d_in[3];
    const float* dones    = (const float*)d_in[4];
    // d_in[5] = prior_noise (unused by reference)
    const float* post_noise = (const float*)d_in[6];
    const float* W_az = (const float*)d_in[7];
    const float* b_az = (const float*)d_in[8];
    const float* W_ih = (const float*)d_in[9];
    const float* W_hh = (const float*)d_in[10];
    const float* b_ih = (const float*)d_in[11];
    const float* b_hh = (const float*)d_in[12];
    const float* W_ha = (const float*)d_in[13];
    const float* b_ha = (const float*)d_in[14];
    const float* W_prior = (const float*)d_in[15];
    const float* b_prior = (const float*)d_in[16];
    const float* W_he = (const float*)d_in[17];
    const float* b_he = (const float*)d_in[18];
    const float* W_post = (const float*)d_in[19];
    const float* b_post = (const float*)d_in[20];
    float* out = (float*)d_out;

    k_init<<<512, 256>>>(prev_z, prev_h);
    k_pack<<<512, 256>>>(W_az, W_ha);
    k_pre_act<<<64, 256>>>(actions, W_az, b_az, W_ha, b_ha);
    k_pre_he<<<dim3(256, 8), 128>>>(emb, W_he, b_he);
    k_x<<<BATCH, 512>>>(dones, 0);

    for (int t = 0; t < TSTEPS; t++) {
        k_gates<<<dim3(4, 48), 128>>>(W_ih, W_hh, b_ih, b_hh);
        k_gru<<<512, 256>>>(out, t);
        k_hahe<<<dim3(8, 16), 128>>>(W_he, t);
        k_heads<<<4, 256>>>(W_prior, b_prior, W_post, b_post, post_noise, dones, out, t);
    }
}

// round 5
// speedup vs baseline: 2.2550x; 2.2550x over previous
#include <cuda_runtime.h>
#include <math.h>

#define ADIM 6
#define ZDIM 32
#define HDIM 512
#define EDIM 1024
#define BATCH 256
#define TSTEPS 64
#define NTHR 256
#define SMEMF 16928
#define SMEMB (SMEMF*4)

#define OFF_Z  (BATCH*TSTEPS*HDIM)
#define ZBLK   (BATCH*TSTEPS*ZDIM)
#define OFF_PM (OFF_Z + ZBLK)
#define OFF_PS (OFF_PM + ZBLK)
#define OFF_QM (OFF_PS + ZBLK)
#define OFF_QS (OFF_QM + ZBLK)

// scratch (device globals; no dynamic allocation). pre* layout: [t][b][h]
__device__ __align__(128) float g_preAZ[TSTEPS*BATCH*HDIM];
__device__ __align__(128) float g_preHA[TSTEPS*BATCH*HDIM];
__device__ __align__(128) float g_preHE[TSTEPS*BATCH*HDIM];
__device__ __align__(128) float g_Gp[4][BATCH*3072];
__device__ __align__(128) float g_Hp[4][BATCH*1024];
__device__ __align__(128) float g_h[BATCH*HDIM];
__device__ __align__(128) float g_x[BATCH*HDIM];
__device__ __align__(128) float g_z[BATCH*ZDIM];
__device__ __align__(128) float g_WazzT[ZDIM*HDIM];   // W_az[:,:32]^T  [k][h]
__device__ __align__(128) float g_Wha[HDIM*HDIM];     // W_ha[:,:512] packed
__device__ unsigned g_arrive = 0;
__device__ volatile unsigned g_epoch = 0;

__device__ __forceinline__ float sigmoidf_(float x) { return 1.f/(1.f+expf(-x)); }
__device__ __forceinline__ float softplusf_(float x) {
    return fmaxf(x, 0.f) + log1pf(expf(-fabsf(x)));
}
__device__ __forceinline__ float4 ld4(const float* p) { return *(const float4*)p; }

// grid barrier: release fence -> arrive -> epoch spin -> acquire fence
__device__ __forceinline__ void gsync(int G) {
    __threadfence();
    __syncthreads();
    if (threadIdx.x == 0) {
        unsigned e = g_epoch;
        if (atomicAdd(&g_arrive, 1u) == (unsigned)(G - 1)) {
            g_arrive = 0;
            __threadfence();
            g_epoch = e + 1;
        } else {
            while (g_epoch == e) __nanosleep(64);
        }
        __threadfence();
    }
    __syncthreads();
}

// 64x128 tile GEMM, 256 thr, BK=16, micro 8x4, reg-prefetch. acc += A*B^T
__device__ __forceinline__ void gemm64x128(
    const float* __restrict__ A, int lda, const float* __restrict__ B, int ldb,
    int KT, float* As, float* Bs, float (&acc)[8][4])
{
    const int tid = threadIdx.x;
    const int lr = tid >> 2, lk = (tid & 3) << 2;
    const int ty = tid >> 5, tx = tid & 31;
    const float* Ap = A + lr*lda + lk;
    const float* B0 = B + lr*ldb + lk;
    const float* B1 = B + (lr + 64)*ldb + lk;
    float4 av = ld4(Ap), b0 = ld4(B0), b1 = ld4(B1);
    #pragma unroll 1
    for (int kt = 1; kt <= KT; kt++) {
        __syncthreads();
        As[(lk+0)*68+lr]=av.x; As[(lk+1)*68+lr]=av.y; As[(lk+2)*68+lr]=av.z; As[(lk+3)*68+lr]=av.w;
        Bs[(lk+0)*132+lr]=b0.x; Bs[(lk+1)*132+lr]=b0.y; Bs[(lk+2)*132+lr]=b0.z; Bs[(lk+3)*132+lr]=b0.w;
        Bs[(lk+0)*132+64+lr]=b1.x; Bs[(lk+1)*132+64+lr]=b1.y; Bs[(lk+2)*132+64+lr]=b1.z; Bs[(lk+3)*132+64+lr]=b1.w;
        __syncthreads();
        if (kt < KT) { av = ld4(Ap + kt*16); b0 = ld4(B0 + kt*16); b1 = ld4(B1 + kt*16); }
        #pragma unroll
        for (int kk = 0; kk < 16; kk++) {
            float a[8], b[4];
            *(float4*)(a)   = ld4(As + kk*68 + ty*8);
            *(float4*)(a+4) = ld4(As + kk*68 + ty*8 + 4);
            *(float4*)(b)   = ld4(Bs + kk*132 + tx*4);
            #pragma unroll
            for (int i = 0; i < 8; i++)
                #pragma unroll
                for (int j = 0; j < 4; j++) acc[i][j] += a[i]*b[j];
        }
    }
}

__device__ __forceinline__ float gru1(float ir, float iz, float inn,
                                      float hr, float hz, float hn, float hp) {
    float r = sigmoidf_(ir + hr);
    float u = sigmoidf_(iz + hz);
    float n = tanhf(inn + r*hn);
    return (1.f - u)*n + u*hp;
}

__global__ __launch_bounds__(NTHR, 2) void rssm_kernel(
    const float* __restrict__ prev_z, const float* __restrict__ prev_h,
    const float* __restrict__ actions, const float* __restrict__ emb,
    const float* __restrict__ dones, const float* __restrict__ post_noise,
    const float* __restrict__ W_az, const float* __restrict__ b_az,
    const float* __restrict__ W_ih, const float* __restrict__ W_hh,
    const float* __restrict__ b_ih, const float* __restrict__ b_hh,
    const float* __restrict__ W_ha, const float* __restrict__ b_ha,
    const float* __restrict__ W_prior, const float* __restrict__ b_prior,
    const float* __restrict__ W_he, const float* __restrict__ b_he,
    const float* __restrict__ W_post, const float* __restrict__ b_post,
    float* __restrict__ out)
{
    extern __shared__ __align__(16) float sm[];
    const int tid = threadIdx.x, bid = blockIdx.x, G = gridDim.x;
    const int gthr = G*NTHR, gtid = bid*NTHR + tid;
    float* As = sm;            // 16*68
    float* Bs = sm + 1100;     // 16*132

    // ===== P0: init, pack, action projections, preHE =====
    for (int i = gtid; i < BATCH*HDIM; i += gthr) g_h[i] = prev_h[i];
    for (int i = gtid; i < BATCH*ZDIM; i += gthr) g_z[i] = prev_z[i];
    for (int i = gtid; i < HDIM*HDIM; i += gthr)
        g_Wha[i] = W_ha[(i >> 9)*(HDIM+ADIM) + (i & 511)];
    for (int i = gtid; i < ZDIM*HDIM; i += gthr)
        g_WazzT[i] = W_az[(i & 511)*(ZDIM+ADIM) + (i >> 9)];
    for (int tt = bid; tt < TSTEPS; tt += G) {
        float* waz = sm, *wha = sm + 3072, *actS = sm + 6144;
        __syncthreads();
        for (int e = tid; e < HDIM*ADIM; e += NTHR) {
            int h = e / ADIM, j = e - h*ADIM;
            waz[e] = W_az[h*(ZDIM+ADIM) + ZDIM + j];
            wha[e] = W_ha[h*(HDIM+ADIM) + HDIM + j];
        }
        for (int e = tid; e < BATCH*ADIM; e += NTHR) {
            int b = e / ADIM, j = e - b*ADIM;
            actS[e] = actions[(b*TSTEPS + tt)*ADIM + j];
        }
        __syncthreads();
        for (int e = tid; e < BATCH*HDIM; e += NTHR) {
            int b = e >> 9, h = e & 511;
            float pa = b_az[h], ph = b_ha[h];
            #pragma unroll
            for (int j = 0; j < ADIM; j++) {
                float a = actS[b*ADIM + j];
                pa += a * waz[h*ADIM + j];
                ph += a * wha[h*ADIM + j];
            }
            int o = (tt*BATCH + b)*HDIM + h;
            g_preAZ[o] = pa; g_preHA[o] = ph;
        }
        __syncthreads();
    }
    // preHE = b_he + e @ W_he[:,512:]^T : 1024 tiles 64x128, K=1024
    for (int task = bid; task < 1024; task += G) {
        int n = task & 3, m = task >> 2;
        float acc[8][4] = {};
        gemm64x128(emb + (size_t)m*64*EDIM, EDIM,
                   W_he + (size_t)n*128*1536 + 512, 1536, 64, As, Bs, acc);
        int ty = tid >> 5, tx = tid & 31;
        float4 bh = ld4(b_he + n*128 + tx*4);
        #pragma unroll
        for (int i = 0; i < 8; i++) {
            int r = m*64 + ty*8 + i;
            int o = ((r & 63)*BATCH + (r >> 6))*HDIM + n*128 + tx*4;
            *(float4*)(g_preHE + o) = make_float4(acc[i][0]+bh.x, acc[i][1]+bh.y,
                                                  acc[i][2]+bh.z, acc[i][3]+bh.w);
        }
    }
    gsync(G);
    // ===== P1: x(0) = relu(zmask @ WzzT + preAZ[0]) =====
    for (int i = gtid; i < BATCH*HDIM; i += gthr) {
        int b = i >> 9, c = i & 511;
        float d = 1.f - dones[b*TSTEPS];
        float acx = g_preAZ[b*HDIM + c];
        #pragma unroll 8
        for (int k = 0; k < ZDIM; k++)
            acx += (g_z[b*ZDIM + k]*d) * g_WazzT[k*HDIM + c];
        g_x[i] = fmaxf(acx, 0.f);
    }
    gsync(G);

    for (int t = 0; t < TSTEPS; t++) {
        // ---- A: gate partials. 384 tasks = 96 tiles x Ksplit4 ----
        for (int task = bid; task < 384; task += G) {
            int kc = task & 3, tile = task >> 2;
            int n = tile % 24, m = tile / 24;
            const float* Aptr = ((n < 12) ? g_x : g_h) + (size_t)m*64*HDIM + kc*128;
            const float* Bptr = ((n < 12) ? W_ih + (size_t)n*128*HDIM
                                          : W_hh + (size_t)(n-12)*128*HDIM) + kc*128;
            float acc[8][4] = {};
            gemm64x128(Aptr, HDIM, Bptr, HDIM, 8, As, Bs, acc);
            int ty = tid >> 5, tx = tid & 31;
            #pragma unroll
            for (int i = 0; i < 8; i++)
                *(float4*)&g_Gp[kc][(m*64 + ty*8 + i)*3072 + n*128 + tx*4] =
                    make_float4(acc[i][0], acc[i][1], acc[i][2], acc[i][3]);
        }
        gsync(G);
        // ---- B: combine + GRU fuse + h_seq ----
        for (int i = gtid; i < BATCH*HDIM/4; i += gthr) {
            int b = i >> 7, j4 = (i & 127) << 2;
            const float* p0 = g_Gp[0] + b*3072 + j4;
            const float* p1 = g_Gp[1] + b*3072 + j4;
            const float* p2 = g_Gp[2] + b*3072 + j4;
            const float* p3 = g_Gp[3] + b*3072 + j4;
            float4 gg[6];
            #pragma unroll
            for (int q = 0; q < 6; q++) {
                float4 a = ld4(p0 + q*512), bb = ld4(p1 + q*512);
                float4 c = ld4(p2 + q*512), dd = ld4(p3 + q*512);
                gg[q] = make_float4(a.x+bb.x+c.x+dd.x, a.y+bb.y+c.y+dd.y,
                                    a.z+bb.z+c.z+dd.z, a.w+bb.w+c.w+dd.w);
            }
            float4 bir = ld4(b_ih + j4), biz = ld4(b_ih + 512 + j4), bin = ld4(b_ih + 1024 + j4);
            float4 bhr = ld4(b_hh + j4), bhz = ld4(b_hh + 512 + j4), bhn = ld4(b_hh + 1024 + j4);
            float4 hp = ld4(g_h + i*4);
            float4 hv;
            hv.x = gru1(gg[0].x+bir.x, gg[1].x+biz.x, gg[2].x+bin.x, gg[3].x+bhr.x, gg[4].x+bhz.x, gg[5].x+bhn.x, hp.x);
            hv.y = gru1(gg[0].y+bir.y, gg[1].y+biz.y, gg[2].y+bin.y, gg[3].y+bhr.y, gg[4].y+bhz.y, gg[5].y+bhn.y, hp.y);
            hv.z = gru1(gg[0].z+bir.z, gg[1].z+biz.z, gg[2].z+bin.z, gg[3].z+bhr.z, gg[4].z+bhz.z, gg[5].z+bhn.z, hp.z);
            hv.w = gru1(gg[0].w+bir.w, gg[1].w+biz.w, gg[2].w+bin.w, gg[3].w+bhr.w, gg[4].w+bhz.w, gg[5].w+bhn.w, hp.w);
            *(float4*)(g_h + i*4) = hv;
            *(float4*)(out + (b*TSTEPS + t)*HDIM + j4) = hv;
        }
        gsync(G);
        // ---- C: hahe partials. 128 tasks = 32 tiles x Ksplit4 ----
        for (int task = bid; task < 128; task += G) {
            int kc = task & 3, tile = task >> 2;
            int n = tile & 7, m = tile >> 3;
            const float* Bptr = (n < 4) ? g_Wha + (size_t)n*128*HDIM + kc*128
                                        : W_he + (size_t)(n-4)*128*1536 + kc*128;
            float acc[8][4] = {};
            gemm64x128(g_h + (size_t)m*64*HDIM + kc*128, HDIM,
                       Bptr, (n < 4) ? HDIM : 1536, 8, As, Bs, acc);
            int ty = tid >> 5, tx = tid & 31;
            #pragma unroll
            for (int i = 0; i < 8; i++)
                *(float4*)&g_Hp[kc][(m*64 + ty*8 + i)*1024 + n*128 + tx*4] =
                    make_float4(acc[i][0], acc[i][1], acc[i][2], acc[i][3]);
        }
        gsync(G);
        // ---- D: per 8 rows: combine+relu, heads GEMM, z, x[t+1]. 32 tasks ----
        for (int task = bid; task < 32; task += G) {
            int r0 = task*8;
            float* A8 = sm;          // 8 x 1028
            float* Ws = sm + 8224;   // 128 x 68 (later reused for Q/zm)
            __syncthreads();
            for (int e = tid; e < 8*1024; e += NTHR) {
                int r = e >> 10, c = e & 1023;
                float v = g_Hp[0][(r0+r)*1024+c] + g_Hp[1][(r0+r)*1024+c]
                        + g_Hp[2][(r0+r)*1024+c] + g_Hp[3][(r0+r)*1024+c];
                v += (c < 512) ? g_preHA[(t*BATCH + r0+r)*HDIM + c]
                               : g_preHE[(t*BATCH + r0+r)*HDIM + c - 512];
                A8[r*1028 + c] = fmaxf(v, 0.f);
            }
            const int c = tid & 127, rg = tid >> 7;
            const int aoff = (c < 64) ? 0 : 512;
            float acc[4] = {};
            for (int ch = 0; ch < 8; ch++) {
                __syncthreads();
                for (int e = tid; e < 2048; e += NTHR) {
                    int c2 = e >> 4, k4 = (e & 15) << 2;
                    const float* Wr = (c2 < 64) ? W_prior + c2*HDIM : W_post + (c2-64)*HDIM;
                    float4 w = ld4(Wr + ch*64 + k4);
                    Ws[c2*68+k4] = w.x; Ws[c2*68+k4+1] = w.y;
                    Ws[c2*68+k4+2] = w.z; Ws[c2*68+k4+3] = w.w;
                }
                __syncthreads();
                const float* ab = A8 + (rg*4)*1028 + aoff + ch*64;
                #pragma unroll
                for (int k4 = 0; k4 < 64; k4 += 4) {
                    float4 w = ld4(Ws + c*68 + k4);
                    #pragma unroll
                    for (int i = 0; i < 4; i++) {
                        float4 a = ld4(ab + i*1028 + k4);
                        acc[i] += a.x*w.x + a.y*w.y + a.z*w.z + a.w*w.w;
                    }
                }
            }
            __syncthreads();
            float bias = (c < 64) ? b_prior[c] : b_post[c-64];
            #pragma unroll
            for (int i = 0; i < 4; i++) {
                int r = rg*4 + i, b = r0 + r;
                float v = acc[i] + bias;
                if (c < 32)       out[OFF_PM + (b*TSTEPS + t)*ZDIM + c] = v;
                else if (c < 64)  out[OFF_PS + (b*TSTEPS + t)*ZDIM + c-32] = softplusf_(v);
                else              Ws[r*64 + (c-64)] = v;  // Q area
            }
            __syncthreads();
            {
                int r = tid >> 5, j = tid & 31, b = r0 + r;
                float qm = Ws[r*64 + j];
                float qs = softplusf_(Ws[r*64 + 32 + j]);
                float z = qm + qs * post_noise[(b*TSTEPS + t)*ZDIM + j];
                int o = (b*TSTEPS + t)*ZDIM + j;
                out[OFF_QM + o] = qm; out[OFF_QS + o] = qs; out[OFF_Z + o] = z;
                if (t + 1 < TSTEPS)
                    Ws[512 + r*32 + j] = z * (1.f - dones[b*TSTEPS + t + 1]);
            }
            __syncthreads();
            if (t + 1 < TSTEPS) {
                for (int e = tid; e < 8*HDIM; e += NTHR) {
                    int r = e >> 9, cc = e & 511;
                    float acx = g_preAZ[((t+1)*BATCH + r0+r)*HDIM + cc];
                    #pragma unroll 8
                    for (int k = 0; k < ZDIM; k++)
                        acx += Ws[512 + r*32 + k] * g_WazzT[k*HDIM + cc];
                    g_x[(r0+r)*HDIM + cc] = fmaxf(acx, 0.f);
                }
            }
            __syncthreads();
        }
        gsync(G);
    }
}

extern "C" void kernel_launch(void* const* d_in, const int* in_sizes, int n_in,
                              void* d_out, int out_size) {
    const float* prev_z = (const float*)d_in[0];
    const float* prev_h = (const float*)d_in[1];
    const float* actions = (const float*)d_in[2];
    const float* emb = (const float*)d_in[3];
    const float* dones = (const float*)d_in[4];
    const float* post_noise = (const float*)d_in[6];
    const float* W_az = (const float*)d_in[7];
    const float* b_az = (const float*)d_in[8];
    const float* W_ih = (const float*)d_in[9];
    const float* W_hh = (const float*)d_in[10];
    const float* b_ih = (const float*)d_in[11];
    const float* b_hh = (const float*)d_in[12];
    const float* W_ha = (const float*)d_in[13];
    const float* b_ha = (const float*)d_in[14];
    const float* W_prior = (const float*)d_in[15];
    const float* b_prior = (const float*)d_in[16];
    const float* W_he = (const float*)d_in[17];
    const float* b_he = (const float*)d_in[18];
    const float* W_post = (const float*)d_in[19];
    const float* b_post = (const float*)d_in[20];
    float* out = (float*)d_out;

    cudaFuncSetAttribute(rssm_kernel, cudaFuncAttributeMaxDynamicSharedMemorySize, SMEMB);
    int dev = 0, nsm = 0, occ = 0;
    cudaGetDevice(&dev);
    cudaDeviceGetAttribute(&nsm, cudaDevAttrMultiProcessorCount, dev);
    cudaOccupancyMaxActiveBlocksPerMultiprocessor(&occ, rssm_kernel, NTHR, SMEMB);
    if (occ < 1) occ = 1;
    int G = nsm * occ;
    if (G > 512) G = 512;
    rssm_kernel<<<G, NTHR, SMEMB>>>(prev_z, prev_h, actions, emb, dones, post_noise,
                                    W_az, b_az, W_ih, W_hh, b_ih, b_hh, W_ha, b_ha,
                                    W_prior, b_prior, W_he, b_he, W_post, b_post, out);
}

// round 8
// speedup vs baseline: 3.0940x; 1.3720x over previous
#include <cuda_runtime.h>
#include <math.h>

#define ADIM 6
#define ZDIM 32
#define HDIM 512
#define EDIM 1024
#define BATCH 256
#define TSTEPS 64
#define NTHR 512
#define SMEMB 53248

#define OFF_Z  (BATCH*TSTEPS*HDIM)
#define OFF_PM (OFF_Z + BATCH*TSTEPS*ZDIM)
#define OFF_PS (OFF_PM + BATCH*TSTEPS*ZDIM)
#define OFF_QM (OFF_PS + BATCH*TSTEPS*ZDIM)
#define OFF_QS (OFF_QM + BATCH*TSTEPS*ZDIM)

typedef unsigned long long ull;

// scratch. pre* layout: [t][b][h]
__device__ __align__(128) float g_preAZ[TSTEPS*BATCH*HDIM];
__device__ __align__(128) float g_preHA[TSTEPS*BATCH*HDIM];
__device__ __align__(128) float g_preHE[TSTEPS*BATCH*HDIM];
__device__ __align__(128) float g_Gp[3][BATCH*3072];
__device__ __align__(128) float g_Hp[8][BATCH*1024];
__device__ __align__(128) float g_h[BATCH*HDIM];
__device__ __align__(128) float g_x[BATCH*HDIM];
__device__ __align__(128) float g_z[BATCH*ZDIM];
__device__ __align__(128) float g_WazzT[ZDIM*HDIM];
__device__ __align__(128) float g_Wha[HDIM*HDIM];
__device__ unsigned g_arrive = 0;
__device__ volatile unsigned g_epoch = 0;

__device__ __forceinline__ float sigmoidf_(float x) { return 1.f/(1.f+expf(-x)); }
__device__ __forceinline__ float softplusf_(float x) {
    return fmaxf(x, 0.f) + log1pf(expf(-fabsf(x)));
}
__device__ __forceinline__ float4 ld4(const float* p) { return *(const float4*)p; }

__device__ __forceinline__ ull pk2(float x) {
    ull r; asm("mov.b64 %0, {%1, %1};" : "=l"(r) : "f"(x)); return r;
}
__device__ __forceinline__ void ffma2(ull &d, ull a, ull b) {
    asm("fma.rn.f32x2 %0, %1, %2, %0;" : "+l"(d) : "l"(a), "l"(b));
}
__device__ __forceinline__ void unpk2(ull v, float &lo, float &hi) {
    asm("mov.b64 {%0, %1}, %2;" : "=f"(lo), "=f"(hi) : "l"(v));
}
union F4U { float4 f; ull u[2]; };

__device__ __forceinline__ void gsync(int G) {
    __threadfence();
    __syncthreads();
    if (threadIdx.x == 0) {
        unsigned e = g_epoch;
        if (atomicAdd(&g_arrive, 1u) == (unsigned)(G - 1)) {
            g_arrive = 0;
            __threadfence();
            g_epoch = e + 1;
        } else {
            while (g_epoch == e) __nanosleep(64);
        }
        __threadfence();
    }
    __syncthreads();
}

// 128x128 tile GEMM, 512 thr, BK=16, micro 8x4 via FFMA2 (M-paired). acc += A*B^T
__device__ __forceinline__ void gemm128(
    const float* __restrict__ A, int lda, const float* __restrict__ B, int ldb,
    int KT, float* As, float* Bs, ull (&acc2)[4][4])
{
    const int tid = threadIdx.x;
    const int lr = tid >> 2, lk = (tid & 3) << 2;
    const int ty = tid >> 5, tx = tid & 31;
    const float* Ap = A + lr*lda + lk;
    const float* Bp = B + lr*ldb + lk;
    float4 av = ld4(Ap), bv = ld4(Bp);
    #pragma unroll 1
    for (int kt = 1; kt <= KT; kt++) {
        __syncthreads();
        As[(lk+0)*132+lr]=av.x; As[(lk+1)*132+lr]=av.y; As[(lk+2)*132+lr]=av.z; As[(lk+3)*132+lr]=av.w;
        Bs[(lk+0)*132+lr]=bv.x; Bs[(lk+1)*132+lr]=bv.y; Bs[(lk+2)*132+lr]=bv.z; Bs[(lk+3)*132+lr]=bv.w;
        __syncthreads();
        if (kt < KT) { av = ld4(Ap + kt*16); bv = ld4(Bp + kt*16); }
        #pragma unroll
        for (int kk = 0; kk < 16; kk++) {
            F4U a0, a1, b;
            a0.f = ld4(As + kk*132 + ty*8);
            a1.f = ld4(As + kk*132 + ty*8 + 4);
            b.f  = ld4(Bs + kk*132 + tx*4);
            ull au0 = a0.u[0], au1 = a0.u[1], au2 = a1.u[0], au3 = a1.u[1];
            ull b0 = pk2(b.f.x), b1 = pk2(b.f.y), b2 = pk2(b.f.z), b3 = pk2(b.f.w);
            ffma2(acc2[0][0], au0, b0); ffma2(acc2[0][1], au0, b1);
            ffma2(acc2[0][2], au0, b2); ffma2(acc2[0][3], au0, b3);
            ffma2(acc2[1][0], au1, b0); ffma2(acc2[1][1], au1, b1);
            ffma2(acc2[1][2], au1, b2); ffma2(acc2[1][3], au1, b3);
            ffma2(acc2[2][0], au2, b0); ffma2(acc2[2][1], au2, b1);
            ffma2(acc2[2][2], au2, b2); ffma2(acc2[2][3], au2, b3);
            ffma2(acc2[3][0], au3, b0); ffma2(acc2[3][1], au3, b1);
            ffma2(acc2[3][2], au3, b2); ffma2(acc2[3][3], au3, b3);
        }
    }
}

// unpack acc2 into r[8][4] (rows ty*8+i, cols tx*4+j)
__device__ __forceinline__ void unpack_acc(ull (&acc2)[4][4], float (&r)[8][4]) {
    #pragma unroll
    for (int ip = 0; ip < 4; ip++)
        #pragma unroll
        for (int j = 0; j < 4; j++)
            unpk2(acc2[ip][j], r[2*ip][j], r[2*ip+1][j]);
}

__device__ __forceinline__ float gru1(float ir, float iz, float inn,
                                      float hr, float hz, float hn, float hp) {
    float rr = sigmoidf_(ir + hr);
    float u = sigmoidf_(iz + hz);
    float n = tanhf(inn + rr*hn);
    return (1.f - u)*n + u*hp;
}

__constant__ int c_kofs[3] = {0, 176, 352};
__constant__ int c_kcnt[3] = {11, 11, 10};

__global__ __launch_bounds__(NTHR, 1) void rssm_kernel(
    const float* __restrict__ prev_z, const float* __restrict__ prev_h,
    const float* __restrict__ actions, const float* __restrict__ emb,
    const float* __restrict__ dones, const float* __restrict__ post_noise,
    const float* __restrict__ W_az, const float* __restrict__ b_az,
    const float* __restrict__ W_ih, const float* __restrict__ W_hh,
    const float* __restrict__ b_ih, const float* __restrict__ b_hh,
    const float* __restrict__ W_ha, const float* __restrict__ b_ha,
    const float* __restrict__ W_prior, const float* __restrict__ b_prior,
    const float* __restrict__ W_he, const float* __restrict__ b_he,
    const float* __restrict__ W_post, const float* __restrict__ b_post,
    float* __restrict__ out)
{
    extern __shared__ __align__(16) float sm[];
    const int tid = threadIdx.x, bid = blockIdx.x, G = gridDim.x;
    const int gthr = G*NTHR, gtid = bid*NTHR + tid;
    float* As = sm;            // 16*132
    float* Bs = sm + 2112;     // 16*132

    // ===== P0: init, pack, action projections, preHE =====
    for (int i = gtid; i < BATCH*HDIM; i += gthr) g_h[i] = prev_h[i];
    for (int i = gtid; i < BATCH*ZDIM; i += gthr) g_z[i] = prev_z[i];
    for (int i = gtid; i < HDIM*HDIM; i += gthr)
        g_Wha[i] = W_ha[(i >> 9)*(HDIM+ADIM) + (i & 511)];
    for (int i = gtid; i < ZDIM*HDIM; i += gthr)
        g_WazzT[i] = W_az[(i & 511)*(ZDIM+ADIM) + (i >> 9)];
    for (int tt = bid; tt < TSTEPS; tt += G) {
        float* waz = sm, *wha = sm + 3072, *actS = sm + 6144;
        __syncthreads();
        for (int e = tid; e < HDIM*ADIM; e += NTHR) {
            int h = e / ADIM, j = e - h*ADIM;
            waz[e] = W_az[h*(ZDIM+ADIM) + ZDIM + j];
            wha[e] = W_ha[h*(HDIM+ADIM) + HDIM + j];
        }
        for (int e = tid; e < BATCH*ADIM; e += NTHR) {
            int b = e / ADIM, j = e - b*ADIM;
            actS[e] = actions[(b*TSTEPS + tt)*ADIM + j];
        }
        __syncthreads();
        for (int e = tid; e < BATCH*HDIM; e += NTHR) {
            int b = e >> 9, h = e & 511;
            float pa = b_az[h], ph = b_ha[h];
            #pragma unroll
            for (int j = 0; j < ADIM; j++) {
                float a = actS[b*ADIM + j];
                pa += a * waz[h*ADIM + j];
                ph += a * wha[h*ADIM + j];
            }
            int o = (tt*BATCH + b)*HDIM + h;
            g_preAZ[o] = pa; g_preHA[o] = ph;
        }
        __syncthreads();
    }
    // preHE: 512 tasks = 128 m-tiles x 4 n-tiles, K=1024 (KT=64)
    for (int task = bid; task < 512; task += G) {
        int n = task & 3, m = task >> 2;
        ull acc2[4][4] = {};
        gemm128(emb + (size_t)m*128*EDIM, EDIM,
                W_he + (size_t)n*128*1536 + 512, 1536, 64, As, Bs, acc2);
        float r[8][4]; unpack_acc(acc2, r);
        int ty = tid >> 5, tx = tid & 31;
        float4 bh = ld4(b_he + n*128 + tx*4);
        #pragma unroll
        for (int i = 0; i < 8; i++) {
            int rr = m*128 + ty*8 + i;
            int o = ((rr & 63)*BATCH + (rr >> 6))*HDIM + n*128 + tx*4;
            *(float4*)(g_preHE + o) = make_float4(r[i][0]+bh.x, r[i][1]+bh.y,
                                                  r[i][2]+bh.z, r[i][3]+bh.w);
        }
    }
    gsync(G);
    // ===== P1: x(0) =====
    for (int i = gtid; i < BATCH*HDIM; i += gthr) {
        int b = i >> 9, c = i & 511;
        float d = 1.f - dones[b*TSTEPS];
        float acx = g_preAZ[b*HDIM + c];
        #pragma unroll 8
        for (int k = 0; k < ZDIM; k++)
            acx += (g_z[b*ZDIM + k]*d) * g_WazzT[k*HDIM + c];
        g_x[i] = fmaxf(acx, 0.f);
    }
    gsync(G);

    for (int t = 0; t < TSTEPS; t++) {
        // ---- A: gate partials. 144 tasks = 48 tiles(128x128) x Ksplit3 ----
        for (int task = bid; task < 144; task += G) {
            int kc = task % 3, tile = task / 3;
            int n = tile % 24, m = tile / 24;
            int ko = c_kofs[kc];
            const float* Aptr = ((n < 12) ? g_x : g_h) + (size_t)m*128*HDIM + ko;
            const float* Bptr = ((n < 12) ? W_ih + (size_t)n*128*HDIM
                                          : W_hh + (size_t)(n-12)*128*HDIM) + ko;
            ull acc2[4][4] = {};
            gemm128(Aptr, HDIM, Bptr, HDIM, c_kcnt[kc], As, Bs, acc2);
            float r[8][4]; unpack_acc(acc2, r);
            int ty = tid >> 5, tx = tid & 31;
            #pragma unroll
            for (int i = 0; i < 8; i++)
                *(float4*)&g_Gp[kc][(m*128 + ty*8 + i)*3072 + n*128 + tx*4] =
                    make_float4(r[i][0], r[i][1], r[i][2], r[i][3]);
        }
        gsync(G);
        // ---- B: combine 3 partials + GRU fuse + h_seq ----
        for (int i = gtid; i < BATCH*HDIM/4; i += gthr) {
            int b = i >> 7, j4 = (i & 127) << 2;
            const float* p0 = g_Gp[0] + b*3072 + j4;
            const float* p1 = g_Gp[1] + b*3072 + j4;
            const float* p2 = g_Gp[2] + b*3072 + j4;
            float4 gg[6];
            #pragma unroll
            for (int q = 0; q < 6; q++) {
                float4 a = ld4(p0 + q*512), bb = ld4(p1 + q*512), c = ld4(p2 + q*512);
                gg[q] = make_float4(a.x+bb.x+c.x, a.y+bb.y+c.y, a.z+bb.z+c.z, a.w+bb.w+c.w);
            }
            float4 bir = ld4(b_ih + j4), biz = ld4(b_ih + 512 + j4), bin = ld4(b_ih + 1024 + j4);
            float4 bhr = ld4(b_hh + j4), bhz = ld4(b_hh + 512 + j4), bhn = ld4(b_hh + 1024 + j4);
            float4 hp = ld4(g_h + i*4);
            float4 hv;
            hv.x = gru1(gg[0].x+bir.x, gg[1].x+biz.x, gg[2].x+bin.x, gg[3].x+bhr.x, gg[4].x+bhz.x, gg[5].x+bhn.x, hp.x);
            hv.y = gru1(gg[0].y+bir.y, gg[1].y+biz.y, gg[2].y+bin.y, gg[3].y+bhr.y, gg[4].y+bhz.y, gg[5].y+bhn.y, hp.y);
            hv.z = gru1(gg[0].z+bir.z, gg[1].z+biz.z, gg[2].z+bin.z, gg[3].z+bhr.z, gg[4].z+bhz.z, gg[5].z+bhn.z, hp.z);
            hv.w = gru1(gg[0].w+bir.w, gg[1].w+biz.w, gg[2].w+bin.w, gg[3].w+bhr.w, gg[4].w+bhz.w, gg[5].w+bhn.w, hp.w);
            *(float4*)(g_h + i*4) = hv;
            *(float4*)(out + (b*TSTEPS + t)*HDIM + j4) = hv;
        }
        gsync(G);
        // ---- C: hahe partials. 128 tasks = 16 tiles(128x128) x Ksplit8 (K=64) ----
        for (int task = bid; task < 128; task += G) {
            int kc = task & 7, tile = task >> 3;
            int n = tile & 7, m = tile >> 3;   // m in {0,1}
            const float* Bptr = (n < 4) ? g_Wha + (size_t)n*128*HDIM + kc*64
                                        : W_he + (size_t)(n-4)*128*1536 + kc*64;
            ull acc2[4][4] = {};
            gemm128(g_h + (size_t)m*128*HDIM + kc*64, HDIM,
                    Bptr, (n < 4) ? HDIM : 1536, 4, As, Bs, acc2);
            float r[8][4]; unpack_acc(acc2, r);
            int ty = tid >> 5, tx = tid & 31;
            #pragma unroll
            for (int i = 0; i < 8; i++)
                *(float4*)&g_Hp[kc][(m*128 + ty*8 + i)*1024 + n*128 + tx*4] =
                    make_float4(r[i][0], r[i][1], r[i][2], r[i][3]);
        }
        gsync(G);
        // ---- D: 64 tasks x 4 rows: combine+relu, heads, z, x[t+1] ----
        for (int task = bid; task < 64; task += G) {
            int r0 = task*4;
            float* A8 = sm;          // 4 x 1028
            float* Ws = sm + 4112;   // 128 x 68
            __syncthreads();
            for (int e = tid; e < 4*1024; e += NTHR) {
                int r = e >> 10, c = e & 1023;
                int ro = (r0 + r)*1024 + c;
                float v = g_Hp[0][ro] + g_Hp[1][ro] + g_Hp[2][ro] + g_Hp[3][ro]
                        + g_Hp[4][ro] + g_Hp[5][ro] + g_Hp[6][ro] + g_Hp[7][ro];
                v += (c < 512) ? g_preHA[(t*BATCH + r0+r)*HDIM + c]
                               : g_preHE[(t*BATCH + r0+r)*HDIM + c - 512];
                A8[r*1028 + c] = fmaxf(v, 0.f);
            }
            const int c = tid & 127, rg = tid >> 7;
            const int aoff = (c < 64) ? 0 : 512;
            float acc = 0.f;
            for (int ch = 0; ch < 8; ch++) {
                __syncthreads();
                for (int e = tid; e < 512; e += NTHR) {
                    int c2 = e >> 2, k4 = (e & 3) << 4;
                    const float* Wr = (c2 < 64) ? W_prior + c2*HDIM : W_post + (c2-64)*HDIM;
                    #pragma unroll
                    for (int q = 0; q < 4; q++) {
                        float4 w = ld4(Wr + ch*64 + k4 + q*4);
                        Ws[c2*68 + k4 + q*4]   = w.x; Ws[c2*68 + k4 + q*4+1] = w.y;
                        Ws[c2*68 + k4 + q*4+2] = w.z; Ws[c2*68 + k4 + q*4+3] = w.w;
                    }
                }
                __syncthreads();
                const float* ab = A8 + rg*1028 + aoff + ch*64;
                #pragma unroll
                for (int k4 = 0; k4 < 64; k4 += 4) {
                    float4 w = ld4(Ws + c*68 + k4);
                    float4 a = ld4(ab + k4);
                    acc += a.x*w.x + a.y*w.y + a.z*w.z + a.w*w.w;
                }
            }
            __syncthreads();
            float* Q  = sm;        // 4 x 64 (A8 dead)
            float* zm = sm + 256;  // 4 x 32
            {
                int b = r0 + rg;
                float v = acc + ((c < 64) ? b_prior[c] : b_post[c-64]);
                if (c < 32)       out[OFF_PM + (b*TSTEPS + t)*ZDIM + c] = v;
                else if (c < 64)  out[OFF_PS + (b*TSTEPS + t)*ZDIM + c-32] = softplusf_(v);
                else              Q[rg*64 + (c-64)] = v;
            }
            __syncthreads();
            if (tid < 128) {
                int r = tid >> 5, j = tid & 31, b = r0 + r;
                float qm = Q[r*64 + j];
                float qs = softplusf_(Q[r*64 + 32 + j]);
                float z = qm + qs * post_noise[(b*TSTEPS + t)*ZDIM + j];
                int o = (b*TSTEPS + t)*ZDIM + j;
                out[OFF_QM + o] = qm; out[OFF_QS + o] = qs; out[OFF_Z + o] = z;
                if (t + 1 < TSTEPS)
                    zm[r*32 + j] = z * (1.f - dones[b*TSTEPS + t + 1]);
            }
            __syncthreads();
            if (t + 1 < TSTEPS) {
                for (int e = tid; e < 4*HDIM; e += NTHR) {
                    int r = e >> 9, cc = e & 511;
                    float acx = g_preAZ[((t+1)*BATCH + r0+r)*HDIM + cc];
                    #pragma unroll 8
                    for (int k = 0; k < ZDIM; k++)
                        acx += zm[r*32 + k] * g_WazzT[k*HDIM + cc];
                    g_x[(r0+r)*HDIM + cc] = fmaxf(acx, 0.f);
                }
            }
            __syncthreads();
        }
        gsync(G);
    }
}

extern "C" void kernel_launch(void* const* d_in, const int* in_sizes, int n_in,
                              void* d_out, int out_size) {
    const float* prev_z = (const float*)d_in[0];
    const float* prev_h = (const float*)d_in[1];
    const float* actions = (const float*)d_in[2];
    const float* emb = (const float*)d_in[3];
    const float* dones = (const float*)d_in[4];
    const float* post_noise = (const float*)d_in[6];
    const float* W_az = (const float*)d_in[7];
    const float* b_az = (const float*)d_in[8];
    const float* W_ih = (const float*)d_in[9];
    const float* W_hh = (const float*)d_in[10];
    const float* b_ih = (const float*)d_in[11];
    const float* b_hh = (const float*)d_in[12];
    const float* W_ha = (const float*)d_in[13];
    const float* b_ha = (const float*)d_in[14];
    const float* W_prior = (const float*)d_in[15];
    const float* b_prior = (const float*)d_in[16];
    const float* W_he = (const float*)d_in[17];
    const float* b_he = (const float*)d_in[18];
    const float* W_post = (const float*)d_in[19];
    const float* b_post = (const float*)d_in[20];
    float* out = (float*)d_out;

    cudaFuncSetAttribute(rssm_kernel, cudaFuncAttributeMaxDynamicSharedMemorySize, SMEMB);
    int dev = 0, nsm = 0, occ = 0;
    cudaGetDevice(&dev);
    cudaDeviceGetAttribute(&nsm, cudaDevAttrMultiProcessorCount, dev);
    cudaOccupancyMaxActiveBlocksPerMultiprocessor(&occ, rssm_kernel, NTHR, SMEMB);
    if (occ < 1) occ = 1;
    int G = nsm * occ;
    if (G > 148) G = 148;
    rssm_kernel<<<G, NTHR, SMEMB>>>(prev_z, prev_h, actions, emb, dones, post_noise,
                                    W_az, b_az, W_ih, W_hh, b_ih, b_hh, W_ha, b_ha,
                                    W_prior, b_prior, W_he, b_he, W_post, b_post, out);
}